// round 7
// baseline (speedup 1.0000x reference)
#include <cuda_runtime.h>
#include <cuda_fp16.h>
#include <stdint.h>

#define S_LEN   4096
#define DMODEL  1024
#define NHEAD   16
#define EHEAD   64
#define TDIM    3072
#define L2E     1.4426950408889634f

// Feature gate: tcgen05 only exists when compiling for the sm_103a target.
#if defined(__CUDA_ARCH__) && (__CUDA_ARCH__ == 1030) && defined(__CUDA_ARCH_FEAT_SM103_ALL)
#define HAS_TCGEN05 1
#else
#define HAS_TCGEN05 0
#endif

// f16 staging buffers
__device__ __half g_xh[S_LEN * DMODEL];           // x, f16 (K-major rows)
__device__ __half g_wht[TDIM * DMODEL];           // w^T, [N][K] f16
__device__ __half g_mh[S_LEN * S_LEN];            // mask * log2e, f16
__device__ __half g_qh[NHEAD * S_LEN * EHEAD];    // q * log2e/8
__device__ __half g_kh[NHEAD * S_LEN * EHEAD];    // k
__device__ __half g_vh[NHEAD * S_LEN * EHEAD];    // v [h][s][e] (legacy path)
__device__ __half g_vt[NHEAD * EHEAD * S_LEN];    // v^T [h][e][s] (tc path)

// ---------------------------------------------------------------------------
// helpers
// ---------------------------------------------------------------------------
__device__ __forceinline__ uint32_t smem_u32(const void* p) {
    return (uint32_t)__cvta_generic_to_shared(p);
}
__device__ __forceinline__ void ldsm4(uint32_t* r, uint32_t addr) {
    asm volatile("ldmatrix.sync.aligned.m8n8.x4.shared.b16 {%0,%1,%2,%3}, [%4];"
                 : "=r"(r[0]), "=r"(r[1]), "=r"(r[2]), "=r"(r[3]) : "r"(addr));
}
__device__ __forceinline__ void ldsm4t(uint32_t* r, uint32_t addr) {
    asm volatile("ldmatrix.sync.aligned.m8n8.x4.trans.shared.b16 {%0,%1,%2,%3}, [%4];"
                 : "=r"(r[0]), "=r"(r[1]), "=r"(r[2]), "=r"(r[3]) : "r"(addr));
}
__device__ __forceinline__ void mma16816(float* c, const uint32_t* a,
                                         uint32_t b0, uint32_t b1) {
    asm volatile(
        "mma.sync.aligned.m16n8k16.row.col.f32.f16.f16.f32 "
        "{%0,%1,%2,%3},{%4,%5,%6,%7},{%8,%9},{%0,%1,%2,%3};"
        : "+f"(c[0]), "+f"(c[1]), "+f"(c[2]), "+f"(c[3])
        : "r"(a[0]), "r"(a[1]), "r"(a[2]), "r"(a[3]), "r"(b0), "r"(b1));
}
#define CP_ASYNC16(s, g) \
    asm volatile("cp.async.cg.shared.global [%0], [%1], 16;\n" :: "r"(s), "l"(g))
#define CP_COMMIT() asm volatile("cp.async.commit_group;\n" ::)
#define CP_WAIT(n)  asm volatile("cp.async.wait_group %0;\n" :: "n"(n))
#define SWZ128(off) ((off) ^ (((off) >> 3) & 0x70))

__device__ __forceinline__ void mbar_wait_g(uint32_t mbar, uint32_t parity) {
    asm volatile(
        "{\n\t.reg .pred P;\n\t"
        "W%=:\n\t"
        "mbarrier.try_wait.parity.shared.b64 P, [%0], %1;\n\t"
        "@!P bra W%=;\n\t}"
        :: "r"(mbar), "r"(parity) : "memory");
}

// ---------------------------------------------------------------------------
// Kernel 0a: convert mask -> f16*log2e, x -> f16
// ---------------------------------------------------------------------------
#define NM4 (S_LEN * S_LEN / 4)
#define NX4 (S_LEN * DMODEL / 4)

__global__ __launch_bounds__(256) void convert_kernel(
    const float* __restrict__ x, const float* __restrict__ mask)
{
    int idx = blockIdx.x * 256 + threadIdx.x;
    if (idx < NM4) {
        float4 v = ((const float4*)mask)[idx];
        *(__half2*)&g_mh[idx * 4]     = __floats2half2_rn(v.x * L2E, v.y * L2E);
        *(__half2*)&g_mh[idx * 4 + 2] = __floats2half2_rn(v.z * L2E, v.w * L2E);
    } else if (idx < NM4 + NX4) {
        int j = idx - NM4;
        float4 v = ((const float4*)x)[j];
        *(__half2*)&g_xh[j * 4]     = __floats2half2_rn(v.x, v.y);
        *(__half2*)&g_xh[j * 4 + 2] = __floats2half2_rn(v.z, v.w);
    }
}

// ---------------------------------------------------------------------------
// Kernel 0b: W transpose: w[K][N] f32 -> g_wht[N][K] f16
// ---------------------------------------------------------------------------
__global__ __launch_bounds__(256) void wconv_kernel(const float* __restrict__ w)
{
    __shared__ __half sh[128 * 65];
    const int tid = threadIdx.x;
    const int k0 = blockIdx.x * 128, n0 = blockIdx.y * 64;
    #pragma unroll
    for (int i = 0; i < 32; i++) {
        int idx = i * 256 + tid;
        int r = idx >> 6, c = idx & 63;
        sh[r * 65 + c] = __float2half_rn(w[(size_t)(k0 + r) * TDIM + n0 + c]);
    }
    __syncthreads();
    #pragma unroll
    for (int i = 0; i < 4; i++) {
        int idx = i * 256 + tid;
        int n = idx >> 4, k8 = (idx & 15) * 8;
        __half th[8];
        #pragma unroll
        for (int j = 0; j < 8; j++) th[j] = sh[(k8 + j) * 65 + n];
        *(uint4*)&g_wht[(size_t)(n0 + n) * DMODEL + k0 + k8] = *(uint4*)th;
    }
}

// ---------------------------------------------------------------------------
// legacy epilogue scatter (PTX-pass fallback)
// ---------------------------------------------------------------------------
__device__ __forceinline__ void qkv_scatter(int col, int r0, float c0, float c1,
                                            float c2, float c3)
{
    int kind = col >> 10, hh = (col >> 6) & 15, e = col & 63;
    size_t i0 = ((size_t)hh * S_LEN + r0) * EHEAD + e;
    size_t i1 = i0 + 8 * EHEAD;
    __half* dst = (kind == 0) ? g_qh : ((kind == 1) ? g_kh : g_vh);
    float s = (kind == 0) ? (L2E / 8.0f) : 1.0f;
    *(__half2*)&dst[i0] = __floats2half2_rn(c0 * s, c1 * s);
    *(__half2*)&dst[i1] = __floats2half2_rn(c2 * s, c3 * s);
}

// ---------------------------------------------------------------------------
// Kernel 1a: QKV GEMM legacy (PTX-pass fallback only)
// ---------------------------------------------------------------------------
#define GL_PITCH 72
#define GL_TILE (128 * GL_PITCH)
#define GL_STAGE (2 * GL_TILE)
#define GEMM_L_SMEM (2 * GL_STAGE * 2)

__global__ __launch_bounds__(256, 2) void qkv_gemm_legacy()
{
#if !HAS_TCGEN05
    extern __shared__ __half sg[];
    const int tid = threadIdx.x, lane = tid & 31, wid = tid >> 5;
    const int bm = blockIdx.y * 128, bn = blockIdx.x * 128;
    const int wm = (wid >> 2) * 64, wn = (wid & 3) * 32;

    float acc[4][4][4];
    #pragma unroll
    for (int a = 0; a < 4; a++)
        #pragma unroll
        for (int b = 0; b < 4; b++)
            #pragma unroll
            for (int c = 0; c < 4; c++) acc[a][b][c] = 0.0f;

    auto load_stage = [&](int st, int k0) {
        __half* A = sg + st * GL_STAGE;
        __half* B = A + GL_TILE;
        #pragma unroll
        for (int i = 0; i < 4; i++) {
            int idx = i * 256 + tid;
            int r = idx >> 3, c8 = (idx & 7) * 8;
            CP_ASYNC16(smem_u32(&A[r * GL_PITCH + c8]),
                       (const void*)&g_xh[(size_t)(bm + r) * DMODEL + k0 + c8]);
            CP_ASYNC16(smem_u32(&B[r * GL_PITCH + c8]),
                       (const void*)&g_wht[(size_t)(bn + r) * DMODEL + k0 + c8]);
        }
    };

    load_stage(0, 0);
    CP_COMMIT();

    const int NIT = DMODEL / 64;
    for (int it = 0; it < NIT; it++) {
        if (it + 1 < NIT) {
            load_stage((it + 1) & 1, (it + 1) * 64);
            CP_COMMIT();
            CP_WAIT(1);
        } else {
            CP_WAIT(0);
        }
        __syncthreads();

        __half* A = sg + (it & 1) * GL_STAGE;
        __half* B = A + GL_TILE;

        #pragma unroll
        for (int kk = 0; kk < 64; kk += 16) {
            uint32_t bf[4][2];
            #pragma unroll
            for (int ng = 0; ng < 2; ng++) {
                int row = wn + ng * 16 + (lane & 7) + ((lane >> 4) << 3);
                int col = kk + ((lane >> 3) & 1) * 8;
                uint32_t t4[4];
                ldsm4(t4, smem_u32(&B[row * GL_PITCH + col]));
                bf[2*ng][0] = t4[0]; bf[2*ng][1] = t4[1];
                bf[2*ng+1][0] = t4[2]; bf[2*ng+1][1] = t4[3];
            }
            #pragma unroll
            for (int mt = 0; mt < 4; mt++) {
                uint32_t af[4];
                int row = wm + mt * 16 + (lane & 15);
                int col = kk + ((lane >> 4) << 3);
                ldsm4(af, smem_u32(&A[row * GL_PITCH + col]));
                #pragma unroll
                for (int nt = 0; nt < 4; nt++)
                    mma16816(acc[mt][nt], af, bf[nt][0], bf[nt][1]);
            }
        }
        __syncthreads();
    }

    #pragma unroll
    for (int mt = 0; mt < 4; mt++) {
        int r0 = bm + wm + mt * 16 + (lane >> 2);
        #pragma unroll
        for (int j = 0; j < 4; j++) {
            int col = bn + wn + j * 8 + 2 * (lane & 3);
            qkv_scatter(col, r0, acc[mt][j][0], acc[mt][j][1],
                        acc[mt][j][2], acc[mt][j][3]);
        }
    }
#endif
}

// ---------------------------------------------------------------------------
// Kernel 1b: QKV GEMM on tcgen05. V written transposed into g_vt.
// ---------------------------------------------------------------------------
#define GT_TILE 16384
#define GT_STAGE (2 * GT_TILE)
#define GEMM_T_SMEM (2048 + 2 * GT_STAGE)

__global__ __launch_bounds__(128, 2) void qkv_gemm_tc()
{
#if HAS_TCGEN05
    extern __shared__ char smg[];
    uint32_t sb = smem_u32(smg);
    uint32_t tb = (sb + 1024) & ~1023u;
    const int tid = threadIdx.x, wid = tid >> 5, lane = tid & 31;
    const int bn = blockIdx.x * 128, bm = blockIdx.y * 128;
    const uint32_t mb[2] = {sb + 8, sb + 16};
    const uint32_t IDESC = (1u << 4) | (16u << 17) | (8u << 24);

    if (wid == 0)
        asm volatile("tcgen05.alloc.cta_group::1.sync.aligned.shared::cta.b32 [%0], %1;"
                     :: "r"(sb), "r"(128u) : "memory");
    if (tid == 0) {
        asm volatile("mbarrier.init.shared.b64 [%0], 1;" :: "r"(mb[0]) : "memory");
        asm volatile("mbarrier.init.shared.b64 [%0], 1;" :: "r"(mb[1]) : "memory");
    }
    __syncthreads();
    uint32_t tmem;
    asm volatile("ld.shared.b32 %0, [%1];" : "=r"(tmem) : "r"(sb));

    auto load_stage = [&](int st, int k0) {
        uint32_t ab = tb + st * GT_STAGE;
        uint32_t bb = ab + GT_TILE;
        #pragma unroll
        for (int i = 0; i < 8; i++) {
            int idx = i * 128 + tid;
            int r = idx >> 3, c16 = idx & 7;
            uint32_t off = SWZ128(r * 128 + c16 * 16);
            CP_ASYNC16(ab + off,
                       (const void*)&g_xh[(size_t)(bm + r) * DMODEL + k0 + c16 * 8]);
            CP_ASYNC16(bb + off,
                       (const void*)&g_wht[(size_t)(bn + r) * DMODEL + k0 + c16 * 8]);
        }
    };

    auto mk_desc = [](uint32_t addr) -> uint64_t {
        const uint64_t BASE = (uint64_t(2) << 61) | (uint64_t(1) << 46)
                            | (uint64_t(64) << 32) | (uint64_t(1) << 16);
        return BASE | ((uint64_t)(addr >> 4) & 0x3FFF);
    };

    load_stage(0, 0);
    CP_COMMIT();

    uint32_t elect;
    asm volatile("{\n\t.reg .pred p;\n\telect.sync _|p, 0xFFFFFFFF;\n\t"
                 "selp.b32 %0, 1, 0, p;\n\t}" : "=r"(elect));

    int ph[2] = {0, 0};
    const int NCH = DMODEL / 64;
    for (int i = 0; i < NCH; i++) {
        if (i + 1 < NCH) {
            if (i >= 1) {
                int b = (i + 1) & 1;
                mbar_wait_g(mb[b], (uint32_t)(ph[b] & 1));
                ph[b]++;
            }
            load_stage((i + 1) & 1, (i + 1) * 64);
            CP_COMMIT();
            CP_WAIT(1);
        } else {
            CP_WAIT(0);
        }
        asm volatile("fence.proxy.async.shared::cta;" ::: "memory");
        __syncthreads();

        if (wid == 0 && elect) {
            uint32_t ab = tb + (i & 1) * GT_STAGE;
            uint64_t ad = mk_desc(ab);
            uint64_t bd = mk_desc(ab + GT_TILE);
            #pragma unroll
            for (int s = 0; s < 4; s++) {
                uint32_t en = (i > 0 || s > 0) ? 1u : 0u;
                asm volatile(
                    "{\n\t.reg .pred p;\n\t"
                    "setp.ne.u32 p, %4, 0;\n\t"
                    "tcgen05.mma.cta_group::1.kind::f16 [%0], %1, %2, %3, {%5,%5,%5,%5}, p;\n\t"
                    "}"
                    :: "r"(tmem), "l"(ad + s * 2), "l"(bd + s * 2), "r"(IDESC),
                       "r"(en), "r"(0u) : "memory");
            }
            asm volatile(
                "tcgen05.commit.cta_group::1.mbarrier::arrive::one.shared::cluster.b64 [%0];"
                :: "r"(mb[i & 1]) : "memory");
        }
    }
    {
        int b = (NCH - 1) & 1;
        mbar_wait_g(mb[b], (uint32_t)(ph[b] & 1));
    }
    asm volatile("tcgen05.fence::after_thread_sync;" ::: "memory");

    const int m = bm + wid * 32 + lane;
    const int kind = bn >> 10;
    const float sc = (kind == 0) ? (L2E / 8.0f) : 1.0f;
    __half* dst = (kind == 0) ? g_qh : g_kh;

    #pragma unroll
    for (int b = 0; b < 4; b++) {
        uint32_t regs[32];
        asm volatile(
            "tcgen05.ld.sync.aligned.32x32b.x32.b32 "
            "{%0, %1, %2, %3, %4, %5, %6, %7, "
            " %8, %9, %10, %11, %12, %13, %14, %15, "
            " %16, %17, %18, %19, %20, %21, %22, %23, "
            " %24, %25, %26, %27, %28, %29, %30, %31}, [%32];"
            : "=r"(regs[0]),  "=r"(regs[1]),  "=r"(regs[2]),  "=r"(regs[3]),
              "=r"(regs[4]),  "=r"(regs[5]),  "=r"(regs[6]),  "=r"(regs[7]),
              "=r"(regs[8]),  "=r"(regs[9]),  "=r"(regs[10]), "=r"(regs[11]),
              "=r"(regs[12]), "=r"(regs[13]), "=r"(regs[14]), "=r"(regs[15]),
              "=r"(regs[16]), "=r"(regs[17]), "=r"(regs[18]), "=r"(regs[19]),
              "=r"(regs[20]), "=r"(regs[21]), "=r"(regs[22]), "=r"(regs[23]),
              "=r"(regs[24]), "=r"(regs[25]), "=r"(regs[26]), "=r"(regs[27]),
              "=r"(regs[28]), "=r"(regs[29]), "=r"(regs[30]), "=r"(regs[31])
            : "r"(tmem + b * 32));
        asm volatile("tcgen05.wait::ld.sync.aligned;" ::: "memory");
        int h  = ((bn >> 6) & 15) + (b >> 1);
        int e0 = (b & 1) * 32;
        if (kind != 2) {
            size_t base = ((size_t)h * S_LEN + m) * EHEAD + e0;
            #pragma unroll
            for (int c8 = 0; c8 < 32; c8 += 8) {
                __half tmp[8];
                #pragma unroll
                for (int j = 0; j < 8; j += 2)
                    *(__half2*)&tmp[j] =
                        __floats2half2_rn(__uint_as_float(regs[c8 + j]) * sc,
                                          __uint_as_float(regs[c8 + j + 1]) * sc);
                *(uint4*)&dst[base + c8] = *(uint4*)tmp;
            }
        } else {
            // V: write transposed into g_vt[h][e][s]
            #pragma unroll
            for (int j = 0; j < 32; j++) {
                int e = e0 + j;
                g_vt[((size_t)(h * EHEAD + e)) * S_LEN + m] =
                    __float2half_rn(__uint_as_float(regs[j]));
            }
        }
    }

    __syncthreads();
    if (tid == 0) {
        asm volatile("mbarrier.inval.shared.b64 [%0];" :: "r"(mb[0]) : "memory");
        asm volatile("mbarrier.inval.shared.b64 [%0];" :: "r"(mb[1]) : "memory");
    }
    __syncthreads();
    if (wid == 0) {
        asm volatile("tcgen05.relinquish_alloc_permit.cta_group::1.sync.aligned;");
        asm volatile("tcgen05.dealloc.cta_group::1.sync.aligned.b32 %0, %1;"
                     :: "r"(tmem), "r"(128u));
    }
#endif
}

// ---------------------------------------------------------------------------
// Kernel 2a: tcgen05 flash attention. Bc=128, Q in TMEM (TS mode),
// S in TMEM f32, softmax via ex2.f16x2, P via smem (SS mode), O in TMEM.
// ---------------------------------------------------------------------------
// smem: ctrl(1KB) | K0(16K) K1(16K) V0(16K) V1(16K) P(32K)
#define AT_K0 0
#define AT_V0 32768
#define AT_P  65536
#define ATTN_T_SMEM (2048 + 98304)

__global__ __launch_bounds__(256, 2) void attn_tc(float* __restrict__ out)
{
#if HAS_TCGEN05
    extern __shared__ char sma[];
    uint32_t sb = smem_u32(sma);
    uint32_t tb = (sb + 1024) & ~1023u;
    const uint32_t mbS = sb + 8, mbO = sb + 16;
    const int tid = threadIdx.x, lane = tid & 31, wid = tid >> 5;
    const int head = blockIdx.x;
    const int bm = blockIdx.y * 128;
    const size_t hb = (size_t)head * S_LEN * EHEAD;
    const uint32_t IDESC_S  = (1u << 4) | (16u << 17) | (8u << 24);  // N=128,M=128
    const uint32_t IDESC_PV = (1u << 4) | (8u << 17)  | (8u << 24);  // N=64, M=128

    if (wid == 0)
        asm volatile("tcgen05.alloc.cta_group::1.sync.aligned.shared::cta.b32 [%0], %1;"
                     :: "r"(sb), "r"(256u) : "memory");
    if (tid == 0) {
        asm volatile("mbarrier.init.shared.b64 [%0], 1;" :: "r"(mbS) : "memory");
        asm volatile("mbarrier.init.shared.b64 [%0], 1;" :: "r"(mbO) : "memory");
    }
    __syncthreads();
    uint32_t tmem;
    asm volatile("ld.shared.b32 %0, [%1];" : "=r"(tmem) : "r"(sb));
    const uint32_t TQ = tmem, TS = tmem + 32, TO = tmem + 160;

    auto mk_desc = [](uint32_t addr) -> uint64_t {
        const uint64_t BASE = (uint64_t(2) << 61) | (uint64_t(1) << 46)
                            | (uint64_t(64) << 32) | (uint64_t(1) << 16);
        return BASE | ((uint64_t)(addr >> 4) & 0x3FFF);
    };
    auto loadK = [&](int st, int kv0) {
        uint32_t kb = tb + AT_K0 + st * 16384;
        #pragma unroll
        for (int i = 0; i < 4; i++) {
            int idx = i * 256 + tid;
            int r = idx >> 3, c16 = idx & 7;
            CP_ASYNC16(kb + SWZ128(r * 128 + c16 * 16),
                       (const void*)&g_kh[hb + (size_t)(kv0 + r) * EHEAD + c16 * 8]);
        }
    };
    auto loadV = [&](int st, int kv0) {
        uint32_t vb = tb + AT_V0 + st * 16384;
        #pragma unroll
        for (int i = 0; i < 4; i++) {
            int idx = i * 256 + tid;
            int e = idx >> 4, c16 = idx & 15;
            uint32_t off = (uint32_t)((e >> 3) + (c16 >> 3) * 8) * 1024
                         + (e & 7) * 128 + (c16 & 7) * 16;
            CP_ASYNC16(vb + SWZ128(off),
                       (const void*)&g_vt[((size_t)(head * EHEAD + e)) * S_LEN
                                          + kv0 + c16 * 8]);
        }
    };

    // Q -> TMEM (warps 0-3)
    if (wid < 4) {
        int r = wid * 32 + lane;
        const uint4* qp = (const uint4*)(g_qh + hb + (size_t)(bm + r) * EHEAD);
        uint32_t q[32];
        #pragma unroll
        for (int t = 0; t < 8; t++) {
            uint4 v = qp[t];
            q[t*4] = v.x; q[t*4+1] = v.y; q[t*4+2] = v.z; q[t*4+3] = v.w;
        }
        asm volatile(
            "tcgen05.st.sync.aligned.32x32b.x32.b32 [%0], "
            "{%1, %2, %3, %4, %5, %6, %7, %8, "
            " %9, %10, %11, %12, %13, %14, %15, %16, "
            " %17, %18, %19, %20, %21, %22, %23, %24, "
            " %25, %26, %27, %28, %29, %30, %31, %32};"
            :: "r"(TQ + ((uint32_t)wid << 21)),
               "r"(q[0]),  "r"(q[1]),  "r"(q[2]),  "r"(q[3]),
               "r"(q[4]),  "r"(q[5]),  "r"(q[6]),  "r"(q[7]),
               "r"(q[8]),  "r"(q[9]),  "r"(q[10]), "r"(q[11]),
               "r"(q[12]), "r"(q[13]), "r"(q[14]), "r"(q[15]),
               "r"(q[16]), "r"(q[17]), "r"(q[18]), "r"(q[19]),
               "r"(q[20]), "r"(q[21]), "r"(q[22]), "r"(q[23]),
               "r"(q[24]), "r"(q[25]), "r"(q[26]), "r"(q[27]),
               "r"(q[28]), "r"(q[29]), "r"(q[30]), "r"(q[31])
            : "memory");
        asm volatile("tcgen05.wait::st.sync.aligned;" ::: "memory");
    }

    // preload: group0 = {K0, V0}, group1 = {K1}
    loadK(0, 0); loadV(0, 0); CP_COMMIT();
    loadK(1, 128); CP_COMMIT();

    asm volatile("tcgen05.fence::before_thread_sync;" ::: "memory");
    __syncthreads();

    uint32_t elect;
    asm volatile("{\n\t.reg .pred p;\n\telect.sync _|p, 0xFFFFFFFF;\n\t"
                 "selp.b32 %0, 1, 0, p;\n\t}" : "=r"(elect));

    const int r = (wid & 3) * 32 + lane;      // q row within tile / TMEM lane
    const int colbase = (wid >> 2) * 64;      // kv-col half owned by this warp
    const uint32_t rowoff = (uint32_t)((r >> 3) + (wid >> 2) * 16) * 1024
                          + (r & 7) * 128;    // P smem row base (blocked atom)
    float lacc = 0.0f;
    int pS = 0, pO = 0;

    const int NIT = S_LEN / 128;   // 32
    for (int it = 0; it < NIT; it++) {
        const int kv0 = it * 128;
        CP_WAIT(1);
        asm volatile("fence.proxy.async.shared::cta;" ::: "memory");
        __syncthreads();

        if (wid == 0 && elect) {
            asm volatile("tcgen05.fence::after_thread_sync;" ::: "memory");
            uint64_t kd = mk_desc(tb + AT_K0 + (it & 1) * 16384);
            #pragma unroll
            for (int s = 0; s < 4; s++) {
                uint32_t en = (s > 0) ? 1u : 0u;
                asm volatile(
                    "{\n\t.reg .pred p;\n\t"
                    "setp.ne.u32 p, %4, 0;\n\t"
                    "tcgen05.mma.cta_group::1.kind::f16 [%0], [%1], %2, %3, {%5,%5,%5,%5}, p;\n\t"
                    "}"
                    :: "r"(TS), "r"(TQ + s * 8), "l"(kd + s * 2), "r"(IDESC_S),
                       "r"(en), "r"(0u) : "memory");
            }
            asm volatile(
                "tcgen05.commit.cta_group::1.mbarrier::arrive::one.shared::cluster.b64 [%0];"
                :: "r"(mbS) : "memory");
        }

        // prefetch mask while S-MMA runs
        const uint4* mp = (const uint4*)(g_mh + (size_t)(bm + r) * S_LEN
                                         + kv0 + colbase);
        uint4 mk[8];
        #pragma unroll
        for (int t = 0; t < 8; t++) mk[t] = mp[t];

        mbar_wait_g(mbS, (uint32_t)(pS & 1)); pS++;
        asm volatile("tcgen05.fence::after_thread_sync;" ::: "memory");

        // read S, softmax -> P words + f32 row-sum partial
        uint32_t p[32];
        #pragma unroll
        for (int t = 0; t < 2; t++) {
            uint32_t s32[32];
            asm volatile(
                "tcgen05.ld.sync.aligned.32x32b.x32.b32 "
                "{%0, %1, %2, %3, %4, %5, %6, %7, "
                " %8, %9, %10, %11, %12, %13, %14, %15, "
                " %16, %17, %18, %19, %20, %21, %22, %23, "
                " %24, %25, %26, %27, %28, %29, %30, %31}, [%32];"
                : "=r"(s32[0]),  "=r"(s32[1]),  "=r"(s32[2]),  "=r"(s32[3]),
                  "=r"(s32[4]),  "=r"(s32[5]),  "=r"(s32[6]),  "=r"(s32[7]),
                  "=r"(s32[8]),  "=r"(s32[9]),  "=r"(s32[10]), "=r"(s32[11]),
                  "=r"(s32[12]), "=r"(s32[13]), "=r"(s32[14]), "=r"(s32[15]),
                  "=r"(s32[16]), "=r"(s32[17]), "=r"(s32[18]), "=r"(s32[19]),
                  "=r"(s32[20]), "=r"(s32[21]), "=r"(s32[22]), "=r"(s32[23]),
                  "=r"(s32[24]), "=r"(s32[25]), "=r"(s32[26]), "=r"(s32[27]),
                  "=r"(s32[28]), "=r"(s32[29]), "=r"(s32[30]), "=r"(s32[31])
                : "r"(TS + colbase + t * 32));
            asm volatile("tcgen05.wait::ld.sync.aligned;" ::: "memory");
            const uint32_t* mw = (const uint32_t*)&mk[t * 4];
            #pragma unroll
            for (int j = 0; j < 16; j++) {
                __half2 a = __floats2half2_rn(__uint_as_float(s32[2*j]),
                                              __uint_as_float(s32[2*j+1]));
                a = __hadd2(a, *(const __half2*)&mw[j]);
                uint32_t u = *(uint32_t*)&a;
                asm("ex2.approx.f16x2 %0, %0;" : "+r"(u));
                p[t * 16 + j] = u;
                float2 pf = __half22float2(*(__half2*)&u);
                lacc += pf.x + pf.y;
            }
        }

        if (it > 0) { mbar_wait_g(mbO, (uint32_t)(pO & 1)); pO++; }

        // prefetch V(it+1) then K(it+2) (order matters for CP_WAIT(1))
        if (it + 1 < NIT) loadV((it + 1) & 1, kv0 + 128);
        CP_COMMIT();
        if (it + 2 < NIT) loadK(it & 1, kv0 + 256);
        CP_COMMIT();

        // store P to smem (blocked-atom SW128 A-operand layout)
        #pragma unroll
        for (int t8 = 0; t8 < 8; t8++) {
            uint32_t off = SWZ128(rowoff + t8 * 16);
            asm volatile("st.shared.v4.b32 [%0], {%1,%2,%3,%4};"
                         :: "r"(tb + AT_P + off),
                            "r"(p[t8*4]), "r"(p[t8*4+1]),
                            "r"(p[t8*4+2]), "r"(p[t8*4+3]) : "memory");
        }
        asm volatile("tcgen05.fence::before_thread_sync;" ::: "memory");
        __syncthreads();
        asm volatile("fence.proxy.async.shared::cta;" ::: "memory");

        if (wid == 0 && elect) {
            uint64_t pd = mk_desc(tb + AT_P);
            uint64_t vd = mk_desc(tb + AT_V0 + (it & 1) * 16384);
            #pragma unroll
            for (int s = 0; s < 8; s++) {
                uint64_t po = (s < 4) ? (uint64_t)(2 * s) : (uint64_t)(1024 + 2 * (s - 4));
                uint64_t vo = (s < 4) ? (uint64_t)(2 * s) : (uint64_t)(512 + 2 * (s - 4));
                uint32_t en = (it > 0 || s > 0) ? 1u : 0u;
                asm volatile(
                    "{\n\t.reg .pred p;\n\t"
                    "setp.ne.u32 p, %4, 0;\n\t"
                    "tcgen05.mma.cta_group::1.kind::f16 [%0], %1, %2, %3, {%5,%5,%5,%5}, p;\n\t"
                    "}"
                    :: "r"(TO), "l"(pd + po), "l"(vd + vo), "r"(IDESC_PV),
                       "r"(en), "r"(0u) : "memory");
            }
            asm volatile(
                "tcgen05.commit.cta_group::1.mbarrier::arrive::one.shared::cluster.b64 [%0];"
                :: "r"(mbO) : "memory");
        }
    }

    mbar_wait_g(mbO, (uint32_t)(pO & 1)); pO++;
    asm volatile("tcgen05.fence::after_thread_sync;" ::: "memory");

    // combine row-sum halves via smem (reuse P region)
    float* lsA = (float*)(sma + (tb - sb) + AT_P);
    float* lsB = lsA + 128;
    if (wid < 4) lsA[r] = lacc; else lsB[r] = lacc;
    __syncthreads();
    float inv = 1.0f / (lsA[r] + lsB[r]);

    // read O and write out
    const int cb = (wid >> 2) * 32;
    uint32_t o32[32];
    asm volatile(
        "tcgen05.ld.sync.aligned.32x32b.x32.b32 "
        "{%0, %1, %2, %3, %4, %5, %6, %7, "
        " %8, %9, %10, %11, %12, %13, %14, %15, "
        " %16, %17, %18, %19, %20, %21, %22, %23, "
        " %24, %25, %26, %27, %28, %29, %30, %31}, [%32];"
        : "=r"(o32[0]),  "=r"(o32[1]),  "=r"(o32[2]),  "=r"(o32[3]),
          "=r"(o32[4]),  "=r"(o32[5]),  "=r"(o32[6]),  "=r"(o32[7]),
          "=r"(o32[8]),  "=r"(o32[9]),  "=r"(o32[10]), "=r"(o32[11]),
          "=r"(o32[12]), "=r"(o32[13]), "=r"(o32[14]), "=r"(o32[15]),
          "=r"(o32[16]), "=r"(o32[17]), "=r"(o32[18]), "=r"(o32[19]),
          "=r"(o32[20]), "=r"(o32[21]), "=r"(o32[22]), "=r"(o32[23]),
          "=r"(o32[24]), "=r"(o32[25]), "=r"(o32[26]), "=r"(o32[27]),
          "=r"(o32[28]), "=r"(o32[29]), "=r"(o32[30]), "=r"(o32[31])
        : "r"(TO + cb));
    asm volatile("tcgen05.wait::ld.sync.aligned;" ::: "memory");

    float* op = out + (size_t)(bm + r) * DMODEL + head * EHEAD + cb;
    #pragma unroll
    for (int t = 0; t < 8; t++) {
        float4 v;
        v.x = __uint_as_float(o32[t*4])   * inv;
        v.y = __uint_as_float(o32[t*4+1]) * inv;
        v.z = __uint_as_float(o32[t*4+2]) * inv;
        v.w = __uint_as_float(o32[t*4+3]) * inv;
        *(float4*)(op + t * 4) = v;
    }

    __syncthreads();
    if (tid == 0) {
        asm volatile("mbarrier.inval.shared.b64 [%0];" :: "r"(mbS) : "memory");
        asm volatile("mbarrier.inval.shared.b64 [%0];" :: "r"(mbO) : "memory");
    }
    __syncthreads();
    if (wid == 0) {
        asm volatile("tcgen05.relinquish_alloc_permit.cta_group::1.sync.aligned;");
        asm volatile("tcgen05.dealloc.cta_group::1.sync.aligned.b32 %0, %1;"
                     :: "r"(tmem), "r"(256u));
    }
#endif
}

// ---------------------------------------------------------------------------
// Kernel 2b: legacy flash attention (PTX-pass fallback only)
// ---------------------------------------------------------------------------
#define A_PITCH 72
#define A_SQ (128 * A_PITCH)
#define A_SKV (64 * A_PITCH)
#define A_STAGE (2 * A_SKV)
#define ATTN_SMEM ((A_SQ + 2 * A_STAGE) * 2)

__global__ __launch_bounds__(256, 2) void attn_mma(float* __restrict__ out)
{
#if !HAS_TCGEN05
    extern __shared__ __half smh[];
    __half* Qs = smh;
    __half* KV = Qs + A_SQ;

    const int tid = threadIdx.x, lane = tid & 31, wid = tid >> 5;
    const int head = blockIdx.x;
    const int bm = blockIdx.y * 128;
    const int wm = wid * 16;
    const size_t hb = (size_t)head * S_LEN * EHEAD;

    auto load_stage = [&](int st, int kv0) {
        __half* Ks = KV + st * A_STAGE;
        __half* Vs = Ks + A_SKV;
        #pragma unroll
        for (int i = 0; i < 2; i++) {
            int idx = i * 256 + tid;
            int r = idx >> 3, c8 = (idx & 7) * 8;
            size_t g = hb + (size_t)(kv0 + r) * EHEAD + c8;
            CP_ASYNC16(smem_u32(&Ks[r * A_PITCH + c8]), (const void*)&g_kh[g]);
            CP_ASYNC16(smem_u32(&Vs[r * A_PITCH + c8]), (const void*)&g_vh[g]);
        }
    };

    load_stage(0, 0);
    CP_COMMIT();

    #pragma unroll
    for (int i = 0; i < 4; i++) {
        int idx = i * 256 + tid;
        int m = idx >> 3, c8 = (idx & 7) * 8;
        *(uint4*)&Qs[m * A_PITCH + c8] =
            *(const uint4*)&g_qh[hb + (size_t)(bm + m) * EHEAD + c8];
    }
    __syncthreads();

    uint32_t qf[4][4];
    #pragma unroll
    for (int kk = 0; kk < 4; kk++) {
        int row = wm + (lane & 15), col = kk * 16 + ((lane >> 4) << 3);
        ldsm4(qf[kk], smem_u32(&Qs[row * A_PITCH + col]));
    }

    float oa[8][4];
    float oal[4];
    #pragma unroll
    for (int j = 0; j < 8; j++)
        #pragma unroll
        for (int c = 0; c < 4; c++) oa[j][c] = 0.0f;
    #pragma unroll
    for (int c = 0; c < 4; c++) oal[c] = 0.0f;

    const __half* mp0 = g_mh + (size_t)(bm + wm + (lane >> 2)) * S_LEN + 2 * (lane & 3);
    const uint32_t ONES = 0x3C003C00u;

    const int NIT = S_LEN / 64;
    for (int it = 0; it < NIT; it++) {
        if (it + 1 < NIT) {
            load_stage((it + 1) & 1, (it + 1) * 64);
            CP_COMMIT();
            CP_WAIT(1);
        } else {
            CP_WAIT(0);
        }
        __syncthreads();

        __half* Ks = KV + (it & 1) * A_STAGE;
        __half* Vs = Ks + A_SKV;
        const int kv0 = it * 64;

        uint32_t mh0[8], mh1[8];
        const __half* mrow0 = mp0 + kv0;
        const __half* mrow1 = mrow0 + 8 * S_LEN;
        #pragma unroll
        for (int j = 0; j < 8; j++) {
            mh0[j] = *(const uint32_t*)(mrow0 + j * 8);
            mh1[j] = *(const uint32_t*)(mrow1 + j * 8);
        }

        float sa[8][4];
        #pragma unroll
        for (int j = 0; j < 8; j++)
            #pragma unroll
            for (int c = 0; c < 4; c++) sa[j][c] = 0.0f;

        #pragma unroll
        for (int kk = 0; kk < 4; kk++) {
            #pragma unroll
            for (int cg = 0; cg < 4; cg++) {
                int row = cg * 16 + (lane & 7) + ((lane >> 4) << 3);
                int col = kk * 16 + ((lane >> 3) & 1) * 8;
                uint32_t b4[4];
                ldsm4(b4, smem_u32(&Ks[row * A_PITCH + col]));
                mma16816(sa[2*cg],   qf[kk], b4[0], b4[1]);
                mma16816(sa[2*cg+1], qf[kk], b4[2], b4[3]);
            }
        }

        uint32_t ph[4][4];
        #pragma unroll
        for (int j = 0; j < 8; j++) {
            __half2 a0 = __floats2half2_rn(sa[j][0], sa[j][1]);
            __half2 a1 = __floats2half2_rn(sa[j][2], sa[j][3]);
            a0 = __hadd2(a0, *(const __half2*)&mh0[j]);
            a1 = __hadd2(a1, *(const __half2*)&mh1[j]);
            uint32_t u0 = *(uint32_t*)&a0, u1 = *(uint32_t*)&a1;
            asm("ex2.approx.f16x2 %0, %0;" : "+r"(u0));
            asm("ex2.approx.f16x2 %0, %0;" : "+r"(u1));
            if (j & 1) { ph[j >> 1][2] = u0; ph[j >> 1][3] = u1; }
            else       { ph[j >> 1][0] = u0; ph[j >> 1][1] = u1; }
        }

        #pragma unroll
        for (int kk = 0; kk < 4; kk++)
            mma16816(oal, ph[kk], ONES, ONES);

        #pragma unroll
        for (int kk = 0; kk < 4; kk++) {
            int row = kk * 16 + (lane & 15);
            int colb = ((lane >> 4) << 3);
            #pragma unroll
            for (int eg = 0; eg < 4; eg++) {
                int col = eg * 16 + colb;
                uint32_t v4[4];
                ldsm4t(v4, smem_u32(&Vs[row * A_PITCH + col]));
                mma16816(oa[2*eg],   ph[kk], v4[0], v4[1]);
                mma16816(oa[2*eg+1], ph[kk], v4[2], v4[3]);
            }
        }
        __syncthreads();
    }

    float inv0 = 1.0f / oal[0], inv1 = 1.0f / oal[2];
    int r0 = bm + wm + (lane >> 2);
    int cb = head * EHEAD + 2 * (lane & 3);
    #pragma unroll
    for (int j = 0; j < 8; j++) {
        float2 o0 = make_float2(oa[j][0] * inv0, oa[j][1] * inv0);
        float2 o1 = make_float2(oa[j][2] * inv1, oa[j][3] * inv1);
        *(float2*)&out[(size_t)r0 * DMODEL + cb + j * 8] = o0;
        *(float2*)&out[(size_t)(r0 + 8) * DMODEL + cb + j * 8] = o1;
    }
#endif
}

// ---------------------------------------------------------------------------
// kernel_launch — dual variants; exactly one body is live per arch pass.
// ---------------------------------------------------------------------------
extern "C" void kernel_launch(void* const* d_in, const int* in_sizes, int n_in,
                              void* d_out, int out_size)
{
    const float* x    = (const float*)d_in[0];   // [1, 4096, 1024]
    const float* mask = (const float*)d_in[1];   // [1, 1, 4096, 4096]
    const float* w    = (const float*)d_in[2];   // [1024, 3072]
    float* out = (float*)d_out;                  // [1, 4096, 1024]
    (void)in_sizes; (void)n_in; (void)out_size;

    static bool attr_set = false;
    if (!attr_set) {
        cudaFuncSetAttribute(qkv_gemm_legacy,
                             cudaFuncAttributeMaxDynamicSharedMemorySize, GEMM_L_SMEM);
        cudaFuncSetAttribute(qkv_gemm_tc,
                             cudaFuncAttributeMaxDynamicSharedMemorySize, GEMM_T_SMEM);
        cudaFuncSetAttribute(attn_tc,
                             cudaFuncAttributeMaxDynamicSharedMemorySize, ATTN_T_SMEM);
        cudaFuncSetAttribute(attn_mma,
                             cudaFuncAttributeMaxDynamicSharedMemorySize, ATTN_SMEM);
        attr_set = true;
    }

    int conv_blocks = (NM4 + NX4 + 255) / 256;
    convert_kernel<<<conv_blocks, 256>>>(x, mask);

    dim3 wgrid(DMODEL / 128, TDIM / 64);
    wconv_kernel<<<wgrid, 256>>>(w);

    dim3 ggrid(TDIM / 128, S_LEN / 128);
    qkv_gemm_tc<<<ggrid, 128, GEMM_T_SMEM>>>();
    qkv_gemm_legacy<<<ggrid, 256, GEMM_L_SMEM>>>();

    dim3 agrid(NHEAD, S_LEN / 128);
    attn_tc<<<agrid, 256, ATTN_T_SMEM>>>(out);
    attn_mma<<<agrid, 256, ATTN_SMEM>>>(out);
}